// round 11
// baseline (speedup 1.0000x reference)
#include <cuda_runtime.h>
#include <cstdint>
#include <cstddef>
#include <math.h>

// Problem constants
constexpr int NB  = 4;
constexpr int NS  = 2048;
constexpr int NDV = 1024;
constexpr int NH  = 16;
constexpr int NDH = 64;
constexpr int NT  = 64;
constexpr int NDT = 768;

// Scratch (device globals: allocation-free rule)
__device__ float g_pool[NB * NDT];
__device__ float g_gate_q[NB * NDV];
__device__ float g_gate_k[NB * NDV];
__device__ float g_wt[(size_t)3 * NDV * NDV];        // [z][nout][k], tf32
__device__ float g_q[(size_t)NB * NH * NS * NDH];   // [bh][s][d]
__device__ float g_k[(size_t)NB * NH * NS * NDH];   // [bh][s][d]
__device__ float g_v[(size_t)NB * NH * NS * NDH];   // [bh][d][s]  (TRANSPOSED)

// ---------------------------------------------------------------------------
// helpers
// ---------------------------------------------------------------------------
__device__ __forceinline__ void cp_async16(void* smem_dst, const void* gmem_src) {
    unsigned int s = (unsigned int)__cvta_generic_to_shared(smem_dst);
    asm volatile("cp.async.cg.shared.global [%0], [%1], 16;\n" :: "r"(s), "l"(gmem_src));
}
__device__ __forceinline__ void cp_commit() {
    asm volatile("cp.async.commit_group;\n");
}
template <int N>
__device__ __forceinline__ void cp_wait() {
    asm volatile("cp.async.wait_group %0;\n" :: "n"(N));
}
// tf32 round (PTX cvt.rna.tf32.f32 needs a .b32 destination)
__device__ __forceinline__ float to_tf32(float x) {
    unsigned r;
    asm("cvt.rna.tf32.f32 %0, %1;" : "=r"(r) : "f"(x));
    return __uint_as_float(r);
}
__device__ __forceinline__ unsigned to_tf32_u(float x) {
    unsigned r;
    asm("cvt.rna.tf32.f32 %0, %1;" : "=r"(r) : "f"(x));
    return r;
}
// D += A*B, m16n8k8 tf32
__device__ __forceinline__ void mma_tf32(float* c, const unsigned* a,
                                         unsigned b0, unsigned b1) {
    asm volatile(
        "mma.sync.aligned.m16n8k8.row.col.f32.tf32.tf32.f32 "
        "{%0,%1,%2,%3}, {%4,%5,%6,%7}, {%8,%9}, {%0,%1,%2,%3};\n"
        : "+f"(c[0]), "+f"(c[1]), "+f"(c[2]), "+f"(c[3])
        : "r"(a[0]), "r"(a[1]), "r"(a[2]), "r"(a[3]), "r"(b0), "r"(b1));
}
// f32-reg variant (same instruction; avoids uint copies for P frags)
__device__ __forceinline__ void mma_tf32f(float* c, const float* a,
                                          unsigned b0, unsigned b1) {
    asm volatile(
        "mma.sync.aligned.m16n8k8.row.col.f32.tf32.tf32.f32 "
        "{%0,%1,%2,%3}, {%4,%5,%6,%7}, {%8,%9}, {%0,%1,%2,%3};\n"
        : "+f"(c[0]), "+f"(c[1]), "+f"(c[2]), "+f"(c[3])
        : "r"(__float_as_uint(a[0])), "r"(__float_as_uint(a[1])),
          "r"(__float_as_uint(a[2])), "r"(__float_as_uint(a[3])),
          "r"(b0), "r"(b1));
}
// ldmatrix x4 (b16 view; addr is per-lane shared-space address)
__device__ __forceinline__ void ldsm_x4(unsigned* r, const void* p) {
    unsigned addr = (unsigned)__cvta_generic_to_shared(p);
    asm volatile("ldmatrix.sync.aligned.m8n8.x4.shared.b16 {%0,%1,%2,%3}, [%4];"
                 : "=r"(r[0]), "=r"(r[1]), "=r"(r[2]), "=r"(r[3]) : "r"(addr));
}

// ---------------------------------------------------------------------------
// Kernel 0: weight transpose  g_wt[z][n][k] = to_tf32(W_z[k][n])
// ---------------------------------------------------------------------------
__global__ void wt_kernel(const float* __restrict__ Wq,
                          const float* __restrict__ Wk,
                          const float* __restrict__ Wv) {
    __shared__ float t[32][33];
    int z = blockIdx.z;
    const float* W = (z == 0) ? Wq : (z == 1) ? Wk : Wv;
    float* out = g_wt + (size_t)z * NDV * NDV;
    int k0 = blockIdx.x * 32, n0 = blockIdx.y * 32;
    int x = threadIdx.x, y = threadIdx.y;       // 32 x 8
#pragma unroll
    for (int i = 0; i < 32; i += 8)
        t[y + i][x] = W[(size_t)(k0 + y + i) * NDV + n0 + x];
    __syncthreads();
#pragma unroll
    for (int i = 0; i < 32; i += 8)
        out[(size_t)(n0 + y + i) * NDV + k0 + x] = to_tf32(t[x][y + i]);
}

// ---------------------------------------------------------------------------
// Kernel 1: masked-mean pool over text tokens.  pool[b,d]
// ---------------------------------------------------------------------------
__global__ void pool_kernel(const float* __restrict__ txt,
                            const float* __restrict__ tmask) {
    int i = blockIdx.x * blockDim.x + threadIdx.x;
    if (i >= NB * NDT) return;
    int b = i / NDT;
    int d = i - b * NDT;
    float s = 0.f, ms = 0.f;
#pragma unroll 4
    for (int t = 0; t < NT; ++t) {
        float mv = tmask[b * NT + t];
        s += txt[((size_t)(b * NT + t)) * NDT + d] * mv;
        ms += mv;
    }
    g_pool[i] = s / ms;
}

// ---------------------------------------------------------------------------
// Kernel 2: gates = 1 + sigmoid(pool @ Wd + bd).  blockIdx.y: 0 = q, 1 = k
// ---------------------------------------------------------------------------
__global__ void gate_kernel(const float* __restrict__ Wdq,
                            const float* __restrict__ bdq,
                            const float* __restrict__ Wdk,
                            const float* __restrict__ bdk) {
    int idx = blockIdx.x * blockDim.x + threadIdx.x;
    if (idx >= NB * NDV) return;
    int which = blockIdx.y;
    int b = idx / NDV;
    int n = idx - b * NDV;
    const float* W  = which ? Wdk : Wdq;
    const float* bb = which ? bdk : bdq;
    float acc = bb[n];
    const float* p = &g_pool[b * NDT];
#pragma unroll 4
    for (int d = 0; d < NDT; ++d)
        acc += p[d] * W[(size_t)d * NDV + n];
    float gate = 1.f + 1.f / (1.f + expf(-acc));
    if (which) g_gate_k[idx] = gate;
    else       g_gate_q[idx] = gate;
}

// ---------------------------------------------------------------------------
// Kernel 3: QKV projection, tf32 mma.sync + ldmatrix.  (unchanged from R10)
// 3-stage cp.async pipeline (DYNAMIC smem, 61440 B), ONE barrier per iter.
// ---------------------------------------------------------------------------
constexpr int QBK = 16;
constexpr int QPT = 20;                     // smem pitch (20 = 4 mod 32 banks)
constexpr int QNIT = NDV / QBK;             // 64
constexpr int QSTG = 3;
constexpr int QTILE = 128 * QPT;            // floats per tile
constexpr int QKV_SMEM_BYTES = QSTG * 2 * QTILE * 4;   // 61440

__global__ void __launch_bounds__(256, 2) qkv_kernel(
        const float* __restrict__ hid,
        const float* __restrict__ bq,
        const float* __restrict__ bk,
        const float* __restrict__ bv) {
    extern __shared__ float qsm[];
    float* As = qsm;                         // [QSTG][QTILE] hid tile [token][k]
    float* Bs = qsm + QSTG * QTILE;          // [QSTG][QTILE] Wt tile  [nout][k]

    int z = blockIdx.z;
    const float* Wt = g_wt + (size_t)z * NDV * NDV;
    const float* bias = (z == 0) ? bq : (z == 1) ? bk : bv;
    const float* gate = (z == 0) ? g_gate_q : (z == 1) ? g_gate_k : nullptr;
    float* out = (z == 0) ? g_q : (z == 1) ? g_k : g_v;

    int m0 = blockIdx.y * 128;              // token base
    int n0 = blockIdx.x * 128;              // nout base
    int tid  = threadIdx.x;
    int warp = tid >> 5;
    int lane = tid & 31;
    int gid  = lane >> 2;
    int tig  = lane & 3;
    int wm = warp & 3;                      // 0..3 (token)
    int wn = warp >> 2;                     // 0..1 (nout)
    int l16 = lane & 15;
    int ah  = (lane >> 4) * 4;
    int l8  = lane & 7;
    int bh4 = ((lane >> 3) & 3) * 4;

    auto issue = [&](int c, int st) {
#pragma unroll
        for (int u = 0; u < 2; ++u) {
            int idx = tid * 2 + u;
            int row = idx >> 2;
            int c4  = (idx & 3) * 4;
            cp_async16(&As[st * QTILE + row * QPT + c4],
                       &hid[(size_t)(m0 + row) * NDV + c * QBK + c4]);
            cp_async16(&Bs[st * QTILE + row * QPT + c4],
                       &Wt[(size_t)(n0 + row) * NDV + c * QBK + c4]);
        }
        cp_commit();
    };

    float c[2][8][4];
#pragma unroll
    for (int mt = 0; mt < 2; ++mt)
#pragma unroll
        for (int nt = 0; nt < 8; ++nt)
#pragma unroll
            for (int r = 0; r < 4; ++r) c[mt][nt][r] = 0.f;

    issue(0, 0);
    issue(1, 1);

    int st = 0;
    for (int it = 0; it < QNIT; ++it) {
        cp_wait<1>();
        __syncthreads();
        int st2 = st + 2; if (st2 >= QSTG) st2 -= QSTG;
        if (it + 2 < QNIT) issue(it + 2, st2);

        const float* Ap = &As[st * QTILE];
        const float* Bp = &Bs[st * QTILE];

        unsigned a[2][2][4];
#pragma unroll
        for (int mt = 0; mt < 2; ++mt) {
#pragma unroll
            for (int kk = 0; kk < 2; ++kk) {
                ldsm_x4(a[mt][kk],
                        &Ap[(wm * 32 + mt * 16 + l16) * QPT + kk * 8 + ah]);
#pragma unroll
                for (int r = 0; r < 4; ++r)
                    a[mt][kk][r] = to_tf32_u(__uint_as_float(a[mt][kk][r]));
            }
        }
        unsigned bfr[8][4];
#pragma unroll
        for (int nt = 0; nt < 8; ++nt)
            ldsm_x4(bfr[nt], &Bp[(wn * 64 + nt * 8 + l8) * QPT + bh4]);

#pragma unroll
        for (int mt = 0; mt < 2; ++mt)
#pragma unroll
            for (int nt = 0; nt < 8; ++nt) {
                mma_tf32(c[mt][nt], a[mt][0], bfr[nt][0], bfr[nt][1]);
                mma_tf32(c[mt][nt], a[mt][1], bfr[nt][2], bfr[nt][3]);
            }

        if (++st == QSTG) st = 0;
    }

    // Epilogue
    int b = m0 >> 11;
#pragma unroll
    for (int mt = 0; mt < 2; ++mt) {
        int tok  = m0 + wm * 32 + mt * 16 + gid;
        int srow = tok & (NS - 1);
#pragma unroll
        for (int nt = 0; nt < 8; ++nt) {
            int col = n0 + wn * 64 + nt * 8 + 2 * tig;
            float g0 = gate ? gate[b * NDV + col]     : 1.f;
            float g1 = gate ? gate[b * NDV + col + 1] : 1.f;
            float b0v = bias[col], b1v = bias[col + 1];
            float v00 = to_tf32((c[mt][nt][0] + b0v) * g0);
            float v01 = to_tf32((c[mt][nt][1] + b1v) * g1);
            float v10 = to_tf32((c[mt][nt][2] + b0v) * g0);
            float v11 = to_tf32((c[mt][nt][3] + b1v) * g1);
            int h = col >> 6, d = col & 63;
            if (z == 2) {
                float* p = out + ((size_t)(b * NH + h) * NDH + d) * NS;
                p[srow]          = v00;
                p[NS + srow]     = v01;
                p[srow + 8]      = v10;
                p[NS + srow + 8] = v11;
            } else {
                float* p = out + ((size_t)(b * NH + h) * NS) * NDH + d;
                *(float2*)&p[(size_t)srow * NDH]       = make_float2(v00, v01);
                *(float2*)&p[(size_t)(srow + 8) * NDH] = make_float2(v10, v11);
            }
        }
    }
}

// ---------------------------------------------------------------------------
// Kernel 4: flash attention, tf32 mma.sync.
// BQ=128 per block, 4 warps, EACH WARP OWNS 32 Q-ROWS (two m16 halves that
// SHARE every ldsm'd K/V B-fragment) -> smem-read and fill bytes per HMMA
// both halved vs R10.  Q frags from gmem; P relayout in-place via quad
// shuffles; 2-stage cp.async K/V; ONE barrier per iteration.
// ---------------------------------------------------------------------------
constexpr int BQ = 128;
constexpr int BK = 64;
constexpr int NTILE = NS / BK;          // 32
constexpr int KP = 68;
constexpr int VP = 68;
constexpr int ATTN_SMEM_FLOATS = 2 * BK * KP + 2 * NDH * VP;
constexpr int ATTN_SMEM_BYTES = ATTN_SMEM_FLOATS * 4;   // 69632

__global__ void __launch_bounds__(128, 2) attn_kernel(
        const float* __restrict__ amask, float* __restrict__ out) {
    extern __shared__ float sm[];
    float* Ks = sm;                           // [2][BK][KP]  (token-major)
    float* Vs = Ks + 2 * BK * KP;             // [2][NDH][VP] (d-major = V^T)

    int bh = blockIdx.y;
    int b  = bh >> 4;
    int h  = bh & 15;
    int q0 = blockIdx.x * BQ;
    int tid  = threadIdx.x;
    int w    = tid >> 5;
    int lane = tid & 31;
    int gid  = lane >> 2;
    int tig  = lane & 3;
    int l8  = lane & 7;
    int bh4 = ((lane >> 3) & 3) * 4;
    int srcl = (lane & ~3) | (tig >> 1);      // quad-local source for P relayout
    bool odd = (tig & 1) != 0;

    const float* Qg = g_q + (size_t)bh * NS * NDH;
    const float* Kg = g_k + (size_t)bh * NS * NDH;
    const float* Vg = g_v + (size_t)bh * NDH * NS;   // [d][s]

    auto issue_kv = [&](int t0, int st) {
#pragma unroll
        for (int u = 0; u < 8; ++u) {
            int idx = tid + u * 128;
            int row = idx >> 4;
            int c4  = (idx & 15) * 4;
            cp_async16(&Ks[(size_t)st * BK * KP + row * KP + c4],
                       &Kg[(size_t)(t0 + row) * NDH + c4]);
            cp_async16(&Vs[(size_t)st * NDH * VP + row * VP + c4],
                       &Vg[(size_t)row * NS + t0 + c4]);
        }
        cp_commit();
    };

    issue_kv(0, 0);

    // Q A-fragments straight from gmem (g_q is tf32 at rest), once.
    // mt half rows: q0 + w*32 + mt*16 + gid (+8)
    unsigned a[2][8][4];
#pragma unroll
    for (int mt = 0; mt < 2; ++mt) {
        const float* Qr0 = Qg + (size_t)(q0 + w * 32 + mt * 16 + gid) * NDH;
        const float* Qr8 = Qr0 + 8 * NDH;
#pragma unroll
        for (int kk = 0; kk < 8; ++kk) {
            a[mt][kk][0] = __float_as_uint(Qr0[kk * 8 + tig]);
            a[mt][kk][1] = __float_as_uint(Qr8[kk * 8 + tig]);
            a[mt][kk][2] = __float_as_uint(Qr0[kk * 8 + tig + 4]);
            a[mt][kk][3] = __float_as_uint(Qr8[kk * 8 + tig + 4]);
        }
    }

    float o[2][8][4];
#pragma unroll
    for (int mt = 0; mt < 2; ++mt)
#pragma unroll
        for (int j = 0; j < 8; ++j)
#pragma unroll
            for (int r = 0; r < 4; ++r) o[mt][j][r] = 0.f;
    float mrow[2][2] = {{-1e30f, -1e30f}, {-1e30f, -1e30f}};
    float lrow[2][2] = {{0.f, 0.f}, {0.f, 0.f}};

    for (int it = 0; it < NTILE; ++it) {
        cp_wait<0>();
        __syncthreads();
        if (it + 1 < NTILE) issue_kv((it + 1) * BK, (it + 1) & 1);
        int st = it & 1;
        const float* Kp = &Ks[(size_t)st * BK * KP];
        const float* Vp = &Vs[(size_t)st * NDH * VP];
        int t0 = it * BK;

        // S = Q @ K^T : each K B-fragment feeds BOTH m-halves
        float s[2][8][4];
#pragma unroll
        for (int nt = 0; nt < 8; ++nt) {
#pragma unroll
            for (int mt = 0; mt < 2; ++mt)
                s[mt][nt][0] = s[mt][nt][1] = s[mt][nt][2] = s[mt][nt][3] = 0.f;
#pragma unroll
            for (int kp = 0; kp < 4; ++kp) {
                unsigned bf[4];
                ldsm_x4(bf, &Kp[(nt * 8 + l8) * KP + kp * 16 + bh4]);
                mma_tf32(s[0][nt], a[0][2 * kp],     bf[0], bf[1]);
                mma_tf32(s[1][nt], a[1][2 * kp],     bf[0], bf[1]);
                mma_tf32(s[0][nt], a[0][2 * kp + 1], bf[2], bf[3]);
                mma_tf32(s[1][nt], a[1][2 * kp + 1], bf[2], bf[3]);
            }
        }

        // scale + mask + online softmax, per m-half
#pragma unroll
        for (int mt = 0; mt < 2; ++mt) {
            float mt0 = -1e30f, mt1 = -1e30f;
#pragma unroll
            for (int nt = 0; nt < 8; ++nt) {
                float2 mk = *(const float2*)&amask[b * NS + t0 + nt * 8 + 2 * tig];
                s[mt][nt][0] = fmaf(s[mt][nt][0], 0.125f, mk.x);
                s[mt][nt][1] = fmaf(s[mt][nt][1], 0.125f, mk.y);
                s[mt][nt][2] = fmaf(s[mt][nt][2], 0.125f, mk.x);
                s[mt][nt][3] = fmaf(s[mt][nt][3], 0.125f, mk.y);
                mt0 = fmaxf(mt0, fmaxf(s[mt][nt][0], s[mt][nt][1]));
                mt1 = fmaxf(mt1, fmaxf(s[mt][nt][2], s[mt][nt][3]));
            }
            mt0 = fmaxf(mt0, __shfl_xor_sync(0xffffffffu, mt0, 1));
            mt0 = fmaxf(mt0, __shfl_xor_sync(0xffffffffu, mt0, 2));
            mt1 = fmaxf(mt1, __shfl_xor_sync(0xffffffffu, mt1, 1));
            mt1 = fmaxf(mt1, __shfl_xor_sync(0xffffffffu, mt1, 2));

            float mn0 = fmaxf(mrow[mt][0], mt0);
            float mn1 = fmaxf(mrow[mt][1], mt1);
            float al0 = __expf(mrow[mt][0] - mn0);
            float al1 = __expf(mrow[mt][1] - mn1);
            mrow[mt][0] = mn0; mrow[mt][1] = mn1;
            lrow[mt][0] *= al0; lrow[mt][1] *= al1;
#pragma unroll
            for (int j = 0; j < 8; ++j) {
                o[mt][j][0] *= al0; o[mt][j][1] *= al0;
                o[mt][j][2] *= al1; o[mt][j][3] *= al1;
            }

            float rs0 = 0.f, rs1 = 0.f;
#pragma unroll
            for (int nt = 0; nt < 8; ++nt) {
                s[mt][nt][0] = to_tf32(__expf(s[mt][nt][0] - mrow[mt][0]));
                s[mt][nt][1] = to_tf32(__expf(s[mt][nt][1] - mrow[mt][0]));
                s[mt][nt][2] = to_tf32(__expf(s[mt][nt][2] - mrow[mt][1]));
                s[mt][nt][3] = to_tf32(__expf(s[mt][nt][3] - mrow[mt][1]));
                rs0 += s[mt][nt][0] + s[mt][nt][1];
                rs1 += s[mt][nt][2] + s[mt][nt][3];
            }
            rs0 += __shfl_xor_sync(0xffffffffu, rs0, 1);
            rs0 += __shfl_xor_sync(0xffffffffu, rs0, 2);
            rs1 += __shfl_xor_sync(0xffffffffu, rs1, 1);
            rs1 += __shfl_xor_sync(0xffffffffu, rs1, 2);
            lrow[mt][0] += rs0;
            lrow[mt][1] += rs1;

            // P relayout C-frag -> A-frag via quad shuffles, IN PLACE.
            // P(gid, c): src lane = gid*4 + (c>>1), reg parity = c&1.
#pragma unroll
            for (int kk = 0; kk < 8; ++kk) {
                float e0 = __shfl_sync(0xffffffffu, s[mt][kk][0], srcl);
                float o0 = __shfl_sync(0xffffffffu, s[mt][kk][1], srcl);
                float e1 = __shfl_sync(0xffffffffu, s[mt][kk][2], srcl);
                float o1 = __shfl_sync(0xffffffffu, s[mt][kk][3], srcl);
                float e2 = __shfl_sync(0xffffffffu, s[mt][kk][0], srcl + 2);
                float o2 = __shfl_sync(0xffffffffu, s[mt][kk][1], srcl + 2);
                float e3 = __shfl_sync(0xffffffffu, s[mt][kk][2], srcl + 2);
                float o3 = __shfl_sync(0xffffffffu, s[mt][kk][3], srcl + 2);
                s[mt][kk][0] = odd ? o0 : e0;
                s[mt][kk][1] = odd ? o1 : e1;
                s[mt][kk][2] = odd ? o2 : e2;
                s[mt][kk][3] = odd ? o3 : e3;
            }
        }

        // O += P @ V : each V B-fragment feeds BOTH m-halves
#pragma unroll
        for (int j = 0; j < 8; ++j) {
#pragma unroll
            for (int kp = 0; kp < 4; ++kp) {
                unsigned bf[4];
                ldsm_x4(bf, &Vp[(j * 8 + l8) * VP + kp * 16 + bh4]);
                mma_tf32f(o[0][j], s[0][2 * kp],     bf[0], bf[1]);
                mma_tf32f(o[1][j], s[1][2 * kp],     bf[0], bf[1]);
                mma_tf32f(o[0][j], s[0][2 * kp + 1], bf[2], bf[3]);
                mma_tf32f(o[1][j], s[1][2 * kp + 1], bf[2], bf[3]);
            }
        }
    }

    // Epilogue: normalize, write [B,S,H*Dh]
#pragma unroll
    for (int mt = 0; mt < 2; ++mt) {
        float inv0 = 1.f / lrow[mt][0];
        float inv1 = 1.f / lrow[mt][1];
        int r0 = q0 + w * 32 + mt * 16 + gid;
#pragma unroll
        for (int j = 0; j < 8; ++j) {
            int col = h * NDH + j * 8 + 2 * tig;
            *(float2*)&out[((size_t)(b * NS + r0)) * NDV + col] =
                make_float2(o[mt][j][0] * inv0, o[mt][j][1] * inv0);
            *(float2*)&out[((size_t)(b * NS + r0 + 8)) * NDV + col] =
                make_float2(o[mt][j][2] * inv1, o[mt][j][3] * inv1);
        }
    }
}

// ---------------------------------------------------------------------------
// Launch
// ---------------------------------------------------------------------------
extern "C" void kernel_launch(void* const* d_in, const int* in_sizes, int n_in,
                              void* d_out, int out_size) {
    const float* hid   = (const float*)d_in[0];
    const float* amask = (const float*)d_in[1];
    const float* txt   = (const float*)d_in[2];
    const float* tmask = (const float*)d_in[3];
    const float* Wq  = (const float*)d_in[4];
    const float* bq  = (const float*)d_in[5];
    const float* Wk  = (const float*)d_in[6];
    const float* bk  = (const float*)d_in[7];
    const float* Wv  = (const float*)d_in[8];
    const float* bv  = (const float*)d_in[9];
    const float* Wdq = (const float*)d_in[10];
    const float* bdq = (const float*)d_in[11];
    const float* Wdk = (const float*)d_in[12];
    const float* bdk = (const float*)d_in[13];
    float* out = (float*)d_out;

    cudaFuncSetAttribute(attn_kernel,
                         cudaFuncAttributeMaxDynamicSharedMemorySize,
                         ATTN_SMEM_BYTES);
    cudaFuncSetAttribute(qkv_kernel,
                         cudaFuncAttributeMaxDynamicSharedMemorySize,
                         QKV_SMEM_BYTES);

    wt_kernel<<<dim3(NDV / 32, NDV / 32, 3), dim3(32, 8)>>>(Wq, Wk, Wv);
    pool_kernel<<<(NB * NDT + 255) / 256, 256>>>(txt, tmask);
    gate_kernel<<<dim3((NB * NDV + 255) / 256, 2), 256>>>(Wdq, bdq, Wdk, bdk);
    qkv_kernel<<<dim3(NDV / 128, (NB * NS) / 128, 3), 256, QKV_SMEM_BYTES>>>(
        hid, bq, bk, bv);
    attn_kernel<<<dim3(NS / BQ, NB * NH), 128, ATTN_SMEM_BYTES>>>(amask, out);
}

// round 14
// speedup vs baseline: 1.7127x; 1.7127x over previous
#include <cuda_runtime.h>
#include <cuda_fp16.h>
#include <cstdint>
#include <cstddef>
#include <math.h>

// Problem constants
constexpr int NB  = 4;
constexpr int NS  = 2048;
constexpr int NDV = 1024;
constexpr int NH  = 16;
constexpr int NDH = 64;
constexpr int NT  = 64;
constexpr int NDT = 768;

// Scratch (device globals: allocation-free rule)
__device__ float  g_pool[NB * NDT];
__device__ float  g_gate_q[NB * NDV];
__device__ float  g_gate_k[NB * NDV];
__device__ __half g_wt[(size_t)3 * NDV * NDV];        // [z][nout][k] fp16
__device__ __half g_hidh[(size_t)NB * NS * NDV];      // hid as fp16
__device__ __half g_q[(size_t)NB * NH * NS * NDH];    // [bh][s][d]
__device__ __half g_k[(size_t)NB * NH * NS * NDH];    // [bh][s][d]
__device__ __half g_v[(size_t)NB * NH * NS * NDH];    // [bh][d][s] (TRANSPOSED)

// ---------------------------------------------------------------------------
// helpers
// ---------------------------------------------------------------------------
__device__ __forceinline__ void cp_async16(void* smem_dst, const void* gmem_src) {
    unsigned int s = (unsigned int)__cvta_generic_to_shared(smem_dst);
    asm volatile("cp.async.cg.shared.global [%0], [%1], 16;\n" :: "r"(s), "l"(gmem_src));
}
__device__ __forceinline__ void cp_commit() {
    asm volatile("cp.async.commit_group;\n");
}
template <int N>
__device__ __forceinline__ void cp_wait() {
    asm volatile("cp.async.wait_group %0;\n" :: "n"(N));
}
// D += A*B, m16n8k16 fp16 -> f32
__device__ __forceinline__ void mma_f16(float* c, const unsigned* a,
                                        unsigned b0, unsigned b1) {
    asm volatile(
        "mma.sync.aligned.m16n8k16.row.col.f32.f16.f16.f32 "
        "{%0,%1,%2,%3}, {%4,%5,%6,%7}, {%8,%9}, {%0,%1,%2,%3};\n"
        : "+f"(c[0]), "+f"(c[1]), "+f"(c[2]), "+f"(c[3])
        : "r"(a[0]), "r"(a[1]), "r"(a[2]), "r"(a[3]), "r"(b0), "r"(b1));
}
// ldmatrix x4 (b16)
__device__ __forceinline__ void ldsm_x4(unsigned* r, const void* p) {
    unsigned addr = (unsigned)__cvta_generic_to_shared(p);
    asm volatile("ldmatrix.sync.aligned.m8n8.x4.shared.b16 {%0,%1,%2,%3}, [%4];"
                 : "=r"(r[0]), "=r"(r[1]), "=r"(r[2]), "=r"(r[3]) : "r"(addr));
}
__device__ __forceinline__ unsigned pack_h2(float lo, float hi) {
    __half2 h = __floats2half2_rn(lo, hi);
    return *(unsigned*)&h;
}

// ---------------------------------------------------------------------------
// Kernel 0a: weight transpose+convert  g_wt[z][n][k] = fp16(W_z[k][n])
// ---------------------------------------------------------------------------
__global__ void wt_kernel(const float* __restrict__ Wq,
                          const float* __restrict__ Wk,
                          const float* __restrict__ Wv) {
    __shared__ float t[32][33];
    int z = blockIdx.z;
    const float* W = (z == 0) ? Wq : (z == 1) ? Wk : Wv;
    __half* out = g_wt + (size_t)z * NDV * NDV;
    int k0 = blockIdx.x * 32, n0 = blockIdx.y * 32;
    int x = threadIdx.x, y = threadIdx.y;       // 32 x 8
#pragma unroll
    for (int i = 0; i < 32; i += 8)
        t[y + i][x] = W[(size_t)(k0 + y + i) * NDV + n0 + x];
    __syncthreads();
#pragma unroll
    for (int i = 0; i < 32; i += 8)
        out[(size_t)(n0 + y + i) * NDV + k0 + x] = __float2half(t[x][y + i]);
}

// ---------------------------------------------------------------------------
// Kernel 0b: hid -> fp16
// ---------------------------------------------------------------------------
__global__ void hidh_kernel(const float* __restrict__ hid) {
    size_t i = ((size_t)blockIdx.x * blockDim.x + threadIdx.x) * 4;
    if (i >= (size_t)NB * NS * NDV) return;
    float4 v = *(const float4*)&hid[i];
    __half2 lo = __floats2half2_rn(v.x, v.y);
    __half2 hi = __floats2half2_rn(v.z, v.w);
    *(__half2*)&g_hidh[i]     = lo;
    *(__half2*)&g_hidh[i + 2] = hi;
}

// ---------------------------------------------------------------------------
// Kernel 1: masked-mean pool over text tokens.  pool[b,d]
// ---------------------------------------------------------------------------
__global__ void pool_kernel(const float* __restrict__ txt,
                            const float* __restrict__ tmask) {
    int i = blockIdx.x * blockDim.x + threadIdx.x;
    if (i >= NB * NDT) return;
    int b = i / NDT;
    int d = i - b * NDT;
    float s = 0.f, ms = 0.f;
#pragma unroll 4
    for (int t = 0; t < NT; ++t) {
        float mv = tmask[b * NT + t];
        s += txt[((size_t)(b * NT + t)) * NDT + d] * mv;
        ms += mv;
    }
    g_pool[i] = s / ms;
}

// ---------------------------------------------------------------------------
// Kernel 2: gates = 1 + sigmoid(pool @ Wd + bd).  blockIdx.y: 0 = q, 1 = k
// ---------------------------------------------------------------------------
__global__ void gate_kernel(const float* __restrict__ Wdq,
                            const float* __restrict__ bdq,
                            const float* __restrict__ Wdk,
                            const float* __restrict__ bdk) {
    int idx = blockIdx.x * blockDim.x + threadIdx.x;
    if (idx >= NB * NDV) return;
    int which = blockIdx.y;
    int b = idx / NDV;
    int n = idx - b * NDV;
    const float* W  = which ? Wdk : Wdq;
    const float* bb = which ? bdk : bdq;
    float acc = bb[n];
    const float* p = &g_pool[b * NDT];
#pragma unroll 4
    for (int d = 0; d < NDT; ++d)
        acc += p[d] * W[(size_t)d * NDV + n];
    float gate = 1.f + 1.f / (1.f + expf(-acc));
    if (which) g_gate_k[idx] = gate;
    else       g_gate_q[idx] = gate;
}

// ---------------------------------------------------------------------------
// Kernel 3: QKV projection via fp16 m16n8k16 mma + ldmatrix.
// Block 128tok x 128nout, 8 warps (4m x 2n), warp 32x64.  K-chunk = 32
// halves (two k16 steps).  3-stage cp.async (dynamic smem), 1 barrier/iter.
// ---------------------------------------------------------------------------
constexpr int QKC  = 32;                    // halves per chunk
constexpr int QPT  = 40;                    // pitch in halves (80B = 20 banks)
constexpr int QNIT = NDV / QKC;             // 32
constexpr int QSTG = 3;
constexpr int QTILE = 128 * QPT;            // halves per tile
constexpr int QKV_SMEM_BYTES = QSTG * 2 * QTILE * 2;   // 61440

__global__ void __launch_bounds__(256, 2) qkv_kernel(
        const float* __restrict__ bq,
        const float* __restrict__ bk,
        const float* __restrict__ bv) {
    extern __shared__ __half qsm[];
    __half* As = qsm;                        // [QSTG][128][QPT]
    __half* Bs = qsm + QSTG * QTILE;         // [QSTG][128][QPT]

    int z = blockIdx.z;
    const __half* Wt = g_wt + (size_t)z * NDV * NDV;
    const float* bias = (z == 0) ? bq : (z == 1) ? bk : bv;
    const float* gate = (z == 0) ? g_gate_q : (z == 1) ? g_gate_k : nullptr;
    __half* out = (z == 0) ? g_q : (z == 1) ? g_k : g_v;

    int m0 = blockIdx.y * 128;
    int n0 = blockIdx.x * 128;
    int tid  = threadIdx.x;
    int warp = tid >> 5;
    int lane = tid & 31;
    int gid  = lane >> 2;
    int tig  = lane & 3;
    int wm = warp & 3;
    int wn = warp >> 2;
    int l16 = lane & 15;
    int l8  = lane & 7;
    int ahh = (lane >> 4) * 8;               // A col offset (halves)
    int brow8 = ((lane >> 4) & 1) * 8;       // B row offset within 16
    int bk8   = ((lane >> 3) & 1) * 8;       // B col offset within k16

    auto issue = [&](int c, int st) {
#pragma unroll
        for (int u = 0; u < 2; ++u) {
            int idx = tid * 2 + u;           // 0..511
            int row = idx >> 2;              // 0..127
            int c16 = idx & 3;               // 16B chunk (8 halves)
            cp_async16(&As[(size_t)st * QTILE + row * QPT + c16 * 8],
                       &g_hidh[(size_t)(m0 + row) * NDV + c * QKC + c16 * 8]);
            cp_async16(&Bs[(size_t)st * QTILE + row * QPT + c16 * 8],
                       &Wt[(size_t)(n0 + row) * NDV + c * QKC + c16 * 8]);
        }
        cp_commit();
    };

    float c[2][8][4];
#pragma unroll
    for (int mt = 0; mt < 2; ++mt)
#pragma unroll
        for (int nt = 0; nt < 8; ++nt)
#pragma unroll
            for (int r = 0; r < 4; ++r) c[mt][nt][r] = 0.f;

    issue(0, 0);
    issue(1, 1);

    int st = 0;
    for (int it = 0; it < QNIT; ++it) {
        cp_wait<1>();
        __syncthreads();
        int st2 = st + 2; if (st2 >= QSTG) st2 -= QSTG;
        if (it + 2 < QNIT) issue(it + 2, st2);

        const __half* Ap = &As[(size_t)st * QTILE];
        const __half* Bp = &Bs[(size_t)st * QTILE];

        // A frags: mt half (16 rows) x ks (k16): x4 = 16x16 halves
        unsigned a[2][2][4];
#pragma unroll
        for (int mt = 0; mt < 2; ++mt)
#pragma unroll
            for (int ks = 0; ks < 2; ++ks)
                ldsm_x4(a[mt][ks],
                        &Ap[(wm * 32 + mt * 16 + l16) * QPT + ks * 16 + ahh]);

        // B frags: ntp pairs (two n8 tiles) x ks: x4
        unsigned bfr[4][2][4];
#pragma unroll
        for (int ntp = 0; ntp < 4; ++ntp)
#pragma unroll
            for (int ks = 0; ks < 2; ++ks)
                ldsm_x4(bfr[ntp][ks],
                        &Bp[(wn * 64 + ntp * 16 + brow8 + l8) * QPT + ks * 16 + bk8]);

#pragma unroll
        for (int mt = 0; mt < 2; ++mt)
#pragma unroll
            for (int ntp = 0; ntp < 4; ++ntp)
#pragma unroll
                for (int ks = 0; ks < 2; ++ks) {
                    mma_f16(c[mt][2 * ntp],     a[mt][ks], bfr[ntp][ks][0], bfr[ntp][ks][1]);
                    mma_f16(c[mt][2 * ntp + 1], a[mt][ks], bfr[ntp][ks][2], bfr[ntp][ks][3]);
                }

        if (++st == QSTG) st = 0;
    }

    // Epilogue: bias + gate, store fp16
    int b = m0 >> 11;
#pragma unroll
    for (int mt = 0; mt < 2; ++mt) {
        int tok  = m0 + wm * 32 + mt * 16 + gid;
        int srow = tok & (NS - 1);
#pragma unroll
        for (int nt = 0; nt < 8; ++nt) {
            int col = n0 + wn * 64 + nt * 8 + 2 * tig;
            float g0 = gate ? gate[b * NDV + col]     : 1.f;
            float g1 = gate ? gate[b * NDV + col + 1] : 1.f;
            float b0v = bias[col], b1v = bias[col + 1];
            float v00 = (c[mt][nt][0] + b0v) * g0;
            float v01 = (c[mt][nt][1] + b1v) * g1;
            float v10 = (c[mt][nt][2] + b0v) * g0;
            float v11 = (c[mt][nt][3] + b1v) * g1;
            int h = col >> 6, d = col & 63;
            if (z == 2) {
                // V: [bh][d][s]
                __half* p = out + ((size_t)(b * NH + h) * NDH + d) * NS;
                p[srow]          = __float2half(v00);
                p[NS + srow]     = __float2half(v01);
                p[srow + 8]      = __float2half(v10);
                p[NS + srow + 8] = __float2half(v11);
            } else {
                // Q/K: [bh][s][d]
                __half* p = out + ((size_t)(b * NH + h) * NS) * NDH + d;
                *(__half2*)&p[(size_t)srow * NDH] = __floats2half2_rn(v00, v01);
                *(__half2*)&p[(size_t)(srow + 8) * NDH] = __floats2half2_rn(v10, v11);
            }
        }
    }
}

// ---------------------------------------------------------------------------
// Kernel 4: flash attention, fp16 m16n8k16.
// BQ=64, 4 warps x 16 q-rows.  Q frags from gmem; P C-frag pairs ARE the
// PV A-frag half2s (no relayout).  2-stage cp.async K/V halves.
// ---------------------------------------------------------------------------
constexpr int BQ = 64;
constexpr int BK = 64;
constexpr int NTILE = NS / BK;          // 32
constexpr int KP = 72;                  // pitch halves (144B = 36 banks)
constexpr int VP = 72;
constexpr int ATTN_SMEM_BYTES = (2 * BK * KP + 2 * NDH * VP) * 2;   // 36864

__global__ void __launch_bounds__(128, 3) attn_kernel(
        const float* __restrict__ amask, float* __restrict__ out) {
    extern __shared__ __half hsm[];
    __half* Ks = hsm;                         // [2][BK][KP]  token-major
    __half* Vs = hsm + 2 * BK * KP;           // [2][NDH][VP] d-major (V^T)

    int bh = blockIdx.y;
    int b  = bh >> 4;
    int h  = bh & 15;
    int q0 = blockIdx.x * BQ;
    int tid  = threadIdx.x;
    int w    = tid >> 5;
    int lane = tid & 31;
    int gid  = lane >> 2;
    int tig  = lane & 3;
    int l8  = lane & 7;
    int brow8 = ((lane >> 4) & 1) * 8;
    int bk8   = ((lane >> 3) & 1) * 8;

    const __half* Qg = g_q + (size_t)bh * NS * NDH;
    const __half* Kg = g_k + (size_t)bh * NS * NDH;
    const __half* Vg = g_v + (size_t)bh * NDH * NS;   // [d][s]

    auto issue_kv = [&](int t0, int st) {
#pragma unroll
        for (int u = 0; u < 8; ++u) {
            int idx = tid + u * 128;         // 0..1023: K chunks then V chunks
            int is_v = idx >> 9;             // 0 or 1
            int r2   = (idx & 511) >> 3;     // 0..63
            int c16  = idx & 7;              // 16B chunk (8 halves)
            if (!is_v)
                cp_async16(&Ks[(size_t)st * BK * KP + r2 * KP + c16 * 8],
                           &Kg[(size_t)(t0 + r2) * NDH + c16 * 8]);
            else
                cp_async16(&Vs[(size_t)st * NDH * VP + r2 * VP + c16 * 8],
                           &Vg[(size_t)r2 * NS + t0 + c16 * 8]);
        }
        cp_commit();
    };

    issue_kv(0, 0);

    // Q A-frags from gmem fp16 (4 k-chunks of 16): half2 loads
    unsigned a[4][4];
    {
        const __half* Qr0 = Qg + (size_t)(q0 + w * 16 + gid) * NDH;
        const __half* Qr8 = Qr0 + 8 * NDH;
#pragma unroll
        for (int kc = 0; kc < 4; ++kc) {
            a[kc][0] = *(const unsigned*)&Qr0[kc * 16 + 2 * tig];
            a[kc][1] = *(const unsigned*)&Qr8[kc * 16 + 2 * tig];
            a[kc][2] = *(const unsigned*)&Qr0[kc * 16 + 8 + 2 * tig];
            a[kc][3] = *(const unsigned*)&Qr8[kc * 16 + 8 + 2 * tig];
        }
    }

    float o[8][4];
#pragma unroll
    for (int j = 0; j < 8; ++j)
#pragma unroll
        for (int r = 0; r < 4; ++r) o[j][r] = 0.f;
    float mrow[2] = {-1e30f, -1e30f};
    float lrow[2] = {0.f, 0.f};

    for (int it = 0; it < NTILE; ++it) {
        cp_wait<0>();
        __syncthreads();
        if (it + 1 < NTILE) issue_kv((it + 1) * BK, (it + 1) & 1);
        int st = it & 1;
        const __half* Kp = &Ks[(size_t)st * BK * KP];
        const __half* Vp = &Vs[(size_t)st * NDH * VP];
        int t0 = it * BK;

        // S = Q @ K^T : B frags x4 serve two n8 tiles per call
        float s[8][4];
#pragma unroll
        for (int nt = 0; nt < 8; ++nt)
            s[nt][0] = s[nt][1] = s[nt][2] = s[nt][3] = 0.f;
#pragma unroll
        for (int ntp = 0; ntp < 4; ++ntp)
#pragma unroll
            for (int kc = 0; kc < 4; ++kc) {
                unsigned bf[4];
                ldsm_x4(bf, &Kp[(ntp * 16 + brow8 + l8) * KP + kc * 16 + bk8]);
                mma_f16(s[2 * ntp],     a[kc], bf[0], bf[1]);
                mma_f16(s[2 * ntp + 1], a[kc], bf[2], bf[3]);
            }

        // scale + mask + online softmax
        float mt0 = -1e30f, mt1 = -1e30f;
#pragma unroll
        for (int nt = 0; nt < 8; ++nt) {
            float2 mk = *(const float2*)&amask[b * NS + t0 + nt * 8 + 2 * tig];
            s[nt][0] = fmaf(s[nt][0], 0.125f, mk.x);
            s[nt][1] = fmaf(s[nt][1], 0.125f, mk.y);
            s[nt][2] = fmaf(s[nt][2], 0.125f, mk.x);
            s[nt][3] = fmaf(s[nt][3], 0.125f, mk.y);
            mt0 = fmaxf(mt0, fmaxf(s[nt][0], s[nt][1]));
            mt1 = fmaxf(mt1, fmaxf(s[nt][2], s[nt][3]));
        }
        mt0 = fmaxf(mt0, __shfl_xor_sync(0xffffffffu, mt0, 1));
        mt0 = fmaxf(mt0, __shfl_xor_sync(0xffffffffu, mt0, 2));
        mt1 = fmaxf(mt1, __shfl_xor_sync(0xffffffffu, mt1, 1));
        mt1 = fmaxf(mt1, __shfl_xor_sync(0xffffffffu, mt1, 2));

        float mn0 = fmaxf(mrow[0], mt0);
        float mn1 = fmaxf(mrow[1], mt1);
        float al0 = __expf(mrow[0] - mn0);
        float al1 = __expf(mrow[1] - mn1);
        mrow[0] = mn0; mrow[1] = mn1;
        lrow[0] *= al0; lrow[1] *= al1;
#pragma unroll
        for (int j = 0; j < 8; ++j) {
            o[j][0] *= al0; o[j][1] *= al0;
            o[j][2] *= al1; o[j][3] *= al1;
        }

        // exp -> half pairs (PV A-frags directly); l-sum over the SAME
        // half-rounded values so normalization cancels the rounding.
        unsigned pa[4][4];                  // [kc][a0..a3]
        float rs0 = 0.f, rs1 = 0.f;
#pragma unroll
        for (int nt = 0; nt < 8; ++nt) {
            float p0 = __expf(s[nt][0] - mrow[0]);
            float p1 = __expf(s[nt][1] - mrow[0]);
            float p2 = __expf(s[nt][2] - mrow[1]);
            float p3 = __expf(s[nt][3] - mrow[1]);
            unsigned lo = pack_h2(p0, p1);
            unsigned hi = pack_h2(p2, p3);
            int kc = nt >> 1;
            if ((nt & 1) == 0) { pa[kc][0] = lo; pa[kc][1] = hi; }
            else               { pa[kc][2] = lo; pa[kc][3] = hi; }
            __half2 hlo = *(__half2*)&lo, hhi = *(__half2*)&hi;
            rs0 += __low2float(hlo) + __high2float(hlo);
            rs1 += __low2float(hhi) + __high2float(hhi);
        }
        rs0 += __shfl_xor_sync(0xffffffffu, rs0, 1);
        rs0 += __shfl_xor_sync(0xffffffffu, rs0, 2);
        rs1 += __shfl_xor_sync(0xffffffffu, rs1, 1);
        rs1 += __shfl_xor_sync(0xffffffffu, rs1, 2);
        lrow[0] += rs0;
        lrow[1] += rs1;

        // O += P @ V : B frags from V^T, x4 serves two d8 tiles
#pragma unroll
        for (int jp = 0; jp < 4; ++jp)
#pragma unroll
            for (int kc = 0; kc < 4; ++kc) {
                unsigned bf[4];
                ldsm_x4(bf, &Vp[(jp * 16 + brow8 + l8) * VP + kc * 16 + bk8]);
                mma_f16(o[2 * jp],     pa[kc], bf[0], bf[1]);
                mma_f16(o[2 * jp + 1], pa[kc], bf[2], bf[3]);
            }
    }

    float inv0 = 1.f / lrow[0];
    float inv1 = 1.f / lrow[1];
    int r0 = q0 + w * 16 + gid;
#pragma unroll
    for (int j = 0; j < 8; ++j) {
        int col = h * NDH + j * 8 + 2 * tig;
        *(float2*)&out[((size_t)(b * NS + r0)) * NDV + col] =
            make_float2(o[j][0] * inv0, o[j][1] * inv0);
        *(float2*)&out[((size_t)(b * NS + r0 + 8)) * NDV + col] =
            make_float2(o[j][2] * inv1, o[j][3] * inv1);
    }
}

// ---------------------------------------------------------------------------
// Launch
// ---------------------------------------------------------------------------
extern "C" void kernel_launch(void* const* d_in, const int* in_sizes, int n_in,
                              void* d_out, int out_size) {
    const float* hid   = (const float*)d_in[0];
    const float* amask = (const float*)d_in[1];
    const float* txt   = (const float*)d_in[2];
    const float* tmask = (const float*)d_in[3];
    const float* Wq  = (const float*)d_in[4];
    const float* bq  = (const float*)d_in[5];
    const float* Wk  = (const float*)d_in[6];
    const float* bk  = (const float*)d_in[7];
    const float* Wv  = (const float*)d_in[8];
    const float* bv  = (const float*)d_in[9];
    const float* Wdq = (const float*)d_in[10];
    const float* bdq = (const float*)d_in[11];
    const float* Wdk = (const float*)d_in[12];
    const float* bdk = (const float*)d_in[13];
    float* out = (float*)d_out;

    cudaFuncSetAttribute(attn_kernel,
                         cudaFuncAttributeMaxDynamicSharedMemorySize,
                         ATTN_SMEM_BYTES);
    cudaFuncSetAttribute(qkv_kernel,
                         cudaFuncAttributeMaxDynamicSharedMemorySize,
                         QKV_SMEM_BYTES);

    wt_kernel<<<dim3(NDV / 32, NDV / 32, 3), dim3(32, 8)>>>(Wq, Wk, Wv);
    hidh_kernel<<<(NB * NS * NDV / 4 + 255) / 256, 256>>>(hid);
    pool_kernel<<<(NB * NDT + 255) / 256, 256>>>(txt, tmask);
    gate_kernel<<<dim3((NB * NDV + 255) / 256, 2), 256>>>(Wdq, bdq, Wdk, bdk);
    qkv_kernel<<<dim3(NDV / 128, (NB * NS) / 128, 3), 256, QKV_SMEM_BYTES>>>(
        bq, bk, bv);
    attn_kernel<<<dim3(NS / BQ, NB * NH), 128, ATTN_SMEM_BYTES>>>(amask, out);
}

// round 15
// speedup vs baseline: 2.0295x; 1.1850x over previous
#include <cuda_runtime.h>
#include <cuda_fp16.h>
#include <cstdint>
#include <cstddef>
#include <math.h>

// Problem constants
constexpr int NB  = 4;
constexpr int NS  = 2048;
constexpr int NDV = 1024;
constexpr int NH  = 16;
constexpr int NDH = 64;
constexpr int NT  = 64;
constexpr int NDT = 768;

// Scratch (device globals: allocation-free rule)
__device__ float  g_pool[NB * NDT];
__device__ float  g_gate_q[NB * NDV];
__device__ float  g_gate_k[NB * NDV];
__device__ __half g_wt[(size_t)3 * NDV * NDV];        // [z][nout][k] fp16
__device__ __half g_hidh[(size_t)NB * NS * NDV];      // hid as fp16
__device__ __half g_q[(size_t)NB * NH * NS * NDH];    // [bh][s][d]
__device__ __half g_k[(size_t)NB * NH * NS * NDH];    // [bh][s][d]
__device__ __half g_v[(size_t)NB * NH * NS * NDH];    // [bh][d][s] (TRANSPOSED)

// ---------------------------------------------------------------------------
// helpers
// ---------------------------------------------------------------------------
__device__ __forceinline__ void cp_async16(void* smem_dst, const void* gmem_src) {
    unsigned int s = (unsigned int)__cvta_generic_to_shared(smem_dst);
    asm volatile("cp.async.cg.shared.global [%0], [%1], 16;\n" :: "r"(s), "l"(gmem_src));
}
__device__ __forceinline__ void cp_commit() {
    asm volatile("cp.async.commit_group;\n");
}
template <int N>
__device__ __forceinline__ void cp_wait() {
    asm volatile("cp.async.wait_group %0;\n" :: "n"(N));
}
// D += A*B, m16n8k16 fp16 -> f32
__device__ __forceinline__ void mma_f16(float* c, const unsigned* a,
                                        unsigned b0, unsigned b1) {
    asm volatile(
        "mma.sync.aligned.m16n8k16.row.col.f32.f16.f16.f32 "
        "{%0,%1,%2,%3}, {%4,%5,%6,%7}, {%8,%9}, {%0,%1,%2,%3};\n"
        : "+f"(c[0]), "+f"(c[1]), "+f"(c[2]), "+f"(c[3])
        : "r"(a[0]), "r"(a[1]), "r"(a[2]), "r"(a[3]), "r"(b0), "r"(b1));
}
// ldmatrix x4 (b16)
__device__ __forceinline__ void ldsm_x4(unsigned* r, const void* p) {
    unsigned addr = (unsigned)__cvta_generic_to_shared(p);
    asm volatile("ldmatrix.sync.aligned.m8n8.x4.shared.b16 {%0,%1,%2,%3}, [%4];"
                 : "=r"(r[0]), "=r"(r[1]), "=r"(r[2]), "=r"(r[3]) : "r"(addr));
}
__device__ __forceinline__ unsigned pack_h2(float lo, float hi) {
    __half2 h = __floats2half2_rn(lo, hi);
    return *(unsigned*)&h;
}

// ---------------------------------------------------------------------------
// Kernel 0a: weight transpose+convert  g_wt[z][n][k] = fp16(W_z[k][n])
// ---------------------------------------------------------------------------
__global__ void wt_kernel(const float* __restrict__ Wq,
                          const float* __restrict__ Wk,
                          const float* __restrict__ Wv) {
    __shared__ float t[32][33];
    int z = blockIdx.z;
    const float* W = (z == 0) ? Wq : (z == 1) ? Wk : Wv;
    __half* out = g_wt + (size_t)z * NDV * NDV;
    int k0 = blockIdx.x * 32, n0 = blockIdx.y * 32;
    int x = threadIdx.x, y = threadIdx.y;       // 32 x 8
#pragma unroll
    for (int i = 0; i < 32; i += 8)
        t[y + i][x] = W[(size_t)(k0 + y + i) * NDV + n0 + x];
    __syncthreads();
#pragma unroll
    for (int i = 0; i < 32; i += 8)
        out[(size_t)(n0 + y + i) * NDV + k0 + x] = __float2half(t[x][y + i]);
}

// ---------------------------------------------------------------------------
// Kernel 0b: hid -> fp16
// ---------------------------------------------------------------------------
__global__ void hidh_kernel(const float* __restrict__ hid) {
    size_t i = ((size_t)blockIdx.x * blockDim.x + threadIdx.x) * 4;
    if (i >= (size_t)NB * NS * NDV) return;
    float4 v = *(const float4*)&hid[i];
    __half2 lo = __floats2half2_rn(v.x, v.y);
    __half2 hi = __floats2half2_rn(v.z, v.w);
    *(__half2*)&g_hidh[i]     = lo;
    *(__half2*)&g_hidh[i + 2] = hi;
}

// ---------------------------------------------------------------------------
// Kernel 1: masked-mean pool over text tokens.  pool[b,d]
// ---------------------------------------------------------------------------
__global__ void pool_kernel(const float* __restrict__ txt,
                            const float* __restrict__ tmask) {
    int i = blockIdx.x * blockDim.x + threadIdx.x;
    if (i >= NB * NDT) return;
    int b = i / NDT;
    int d = i - b * NDT;
    float s = 0.f, ms = 0.f;
#pragma unroll 8
    for (int t = 0; t < NT; ++t) {
        float mv = tmask[b * NT + t];
        s += txt[((size_t)(b * NT + t)) * NDT + d] * mv;
        ms += mv;
    }
    g_pool[i] = s / ms;
}

// ---------------------------------------------------------------------------
// Kernel 2: gates = 1 + sigmoid(pool @ Wd + bd).
// Parallelized: grid (16 n-blocks, 2 which, NB batch), 256 thr =
// 16 n-quads (float4 W loads) x 16 k-groups of 48; smem reduce.
// ---------------------------------------------------------------------------
__global__ void __launch_bounds__(256) gate_kernel(
        const float* __restrict__ Wdq, const float* __restrict__ bdq,
        const float* __restrict__ Wdk, const float* __restrict__ bdk) {
    __shared__ float ps[NDT];            // pool row for this batch
    __shared__ float red[16][64];        // partials [group][n-within-block]

    int bx    = blockIdx.x;              // n-block of 64
    int which = blockIdx.y;
    int b     = blockIdx.z;
    const float* W  = which ? Wdk : Wdq;
    const float* bb = which ? bdk : bdq;
    int tid = threadIdx.x;

    for (int i = tid; i < NDT; i += 256)
        ps[i] = g_pool[b * NDT + i];
    __syncthreads();

    int nq = tid & 15;                   // n-quad 0..15
    int g  = tid >> 4;                   // k-group 0..15 (48 k each)
    int n  = bx * 64 + nq * 4;
    float4 acc = make_float4(0.f, 0.f, 0.f, 0.f);
    int d0 = g * 48;
#pragma unroll 8
    for (int d = d0; d < d0 + 48; ++d) {
        float p = ps[d];
        float4 wv = *(const float4*)&W[(size_t)d * NDV + n];
        acc.x += p * wv.x; acc.y += p * wv.y;
        acc.z += p * wv.z; acc.w += p * wv.w;
    }
    *(float4*)&red[g][nq * 4] = acc;
    __syncthreads();

    if (tid < 64) {
        float s = 0.f;
#pragma unroll
        for (int g2 = 0; g2 < 16; ++g2) s += red[g2][tid];
        int col = bx * 64 + tid;
        float gate = 1.f + 1.f / (1.f + expf(-(s + bb[col])));
        (which ? g_gate_k : g_gate_q)[b * NDV + col] = gate;
    }
}

// ---------------------------------------------------------------------------
// Kernel 3: QKV projection via fp16 m16n8k16 mma + ldmatrix.
// Block 128tok x 128nout, 8 warps (4m x 2n), warp 32x64.  K-chunk = 32
// halves (two k16 steps).  3-stage cp.async (dynamic smem), 1 barrier/iter.
// ---------------------------------------------------------------------------
constexpr int QKC  = 32;                    // halves per chunk
constexpr int QPT  = 40;                    // pitch in halves (80B = 20 banks)
constexpr int QNIT = NDV / QKC;             // 32
constexpr int QSTG = 3;
constexpr int QTILE = 128 * QPT;            // halves per tile
constexpr int QKV_SMEM_BYTES = QSTG * 2 * QTILE * 2;   // 61440

__global__ void __launch_bounds__(256, 2) qkv_kernel(
        const float* __restrict__ bq,
        const float* __restrict__ bk,
        const float* __restrict__ bv) {
    extern __shared__ __half qsm[];
    __half* As = qsm;                        // [QSTG][128][QPT]
    __half* Bs = qsm + QSTG * QTILE;         // [QSTG][128][QPT]

    int z = blockIdx.z;
    const __half* Wt = g_wt + (size_t)z * NDV * NDV;
    const float* bias = (z == 0) ? bq : (z == 1) ? bk : bv;
    const float* gate = (z == 0) ? g_gate_q : (z == 1) ? g_gate_k : nullptr;
    __half* out = (z == 0) ? g_q : (z == 1) ? g_k : g_v;

    int m0 = blockIdx.y * 128;
    int n0 = blockIdx.x * 128;
    int tid  = threadIdx.x;
    int warp = tid >> 5;
    int lane = tid & 31;
    int gid  = lane >> 2;
    int tig  = lane & 3;
    int wm = warp & 3;
    int wn = warp >> 2;
    int l16 = lane & 15;
    int l8  = lane & 7;
    int ahh = (lane >> 4) * 8;               // A col offset (halves)
    int brow8 = ((lane >> 4) & 1) * 8;       // B row offset within 16
    int bk8   = ((lane >> 3) & 1) * 8;       // B col offset within k16

    auto issue = [&](int c, int st) {
#pragma unroll
        for (int u = 0; u < 2; ++u) {
            int idx = tid * 2 + u;           // 0..511
            int row = idx >> 2;              // 0..127
            int c16 = idx & 3;               // 16B chunk (8 halves)
            cp_async16(&As[(size_t)st * QTILE + row * QPT + c16 * 8],
                       &g_hidh[(size_t)(m0 + row) * NDV + c * QKC + c16 * 8]);
            cp_async16(&Bs[(size_t)st * QTILE + row * QPT + c16 * 8],
                       &Wt[(size_t)(n0 + row) * NDV + c * QKC + c16 * 8]);
        }
        cp_commit();
    };

    float c[2][8][4];
#pragma unroll
    for (int mt = 0; mt < 2; ++mt)
#pragma unroll
        for (int nt = 0; nt < 8; ++nt)
#pragma unroll
            for (int r = 0; r < 4; ++r) c[mt][nt][r] = 0.f;

    issue(0, 0);
    issue(1, 1);

    int st = 0;
    for (int it = 0; it < QNIT; ++it) {
        cp_wait<1>();
        __syncthreads();
        int st2 = st + 2; if (st2 >= QSTG) st2 -= QSTG;
        if (it + 2 < QNIT) issue(it + 2, st2);

        const __half* Ap = &As[(size_t)st * QTILE];
        const __half* Bp = &Bs[(size_t)st * QTILE];

        // A frags: mt half (16 rows) x ks (k16): x4 = 16x16 halves
        unsigned a[2][2][4];
#pragma unroll
        for (int mt = 0; mt < 2; ++mt)
#pragma unroll
            for (int ks = 0; ks < 2; ++ks)
                ldsm_x4(a[mt][ks],
                        &Ap[(wm * 32 + mt * 16 + l16) * QPT + ks * 16 + ahh]);

        // B frags: ntp pairs (two n8 tiles) x ks: x4
        unsigned bfr[4][2][4];
#pragma unroll
        for (int ntp = 0; ntp < 4; ++ntp)
#pragma unroll
            for (int ks = 0; ks < 2; ++ks)
                ldsm_x4(bfr[ntp][ks],
                        &Bp[(wn * 64 + ntp * 16 + brow8 + l8) * QPT + ks * 16 + bk8]);

#pragma unroll
        for (int mt = 0; mt < 2; ++mt)
#pragma unroll
            for (int ntp = 0; ntp < 4; ++ntp)
#pragma unroll
                for (int ks = 0; ks < 2; ++ks) {
                    mma_f16(c[mt][2 * ntp],     a[mt][ks], bfr[ntp][ks][0], bfr[ntp][ks][1]);
                    mma_f16(c[mt][2 * ntp + 1], a[mt][ks], bfr[ntp][ks][2], bfr[ntp][ks][3]);
                }

        if (++st == QSTG) st = 0;
    }

    // Epilogue: bias + gate, store fp16
    int b = m0 >> 11;
#pragma unroll
    for (int mt = 0; mt < 2; ++mt) {
        int tok  = m0 + wm * 32 + mt * 16 + gid;
        int srow = tok & (NS - 1);
#pragma unroll
        for (int nt = 0; nt < 8; ++nt) {
            int col = n0 + wn * 64 + nt * 8 + 2 * tig;
            float g0 = gate ? gate[b * NDV + col]     : 1.f;
            float g1 = gate ? gate[b * NDV + col + 1] : 1.f;
            float b0v = bias[col], b1v = bias[col + 1];
            float v00 = (c[mt][nt][0] + b0v) * g0;
            float v01 = (c[mt][nt][1] + b1v) * g1;
            float v10 = (c[mt][nt][2] + b0v) * g0;
            float v11 = (c[mt][nt][3] + b1v) * g1;
            int h = col >> 6, d = col & 63;
            if (z == 2) {
                // V: [bh][d][s]
                __half* p = out + ((size_t)(b * NH + h) * NDH + d) * NS;
                p[srow]          = __float2half(v00);
                p[NS + srow]     = __float2half(v01);
                p[srow + 8]      = __float2half(v10);
                p[NS + srow + 8] = __float2half(v11);
            } else {
                // Q/K: [bh][s][d]
                __half* p = out + ((size_t)(b * NH + h) * NS) * NDH + d;
                *(__half2*)&p[(size_t)srow * NDH] = __floats2half2_rn(v00, v01);
                *(__half2*)&p[(size_t)(srow + 8) * NDH] = __floats2half2_rn(v10, v11);
            }
        }
    }
}

// ---------------------------------------------------------------------------
// Kernel 4: flash attention, fp16 m16n8k16.
// BQ=64, 4 warps x 16 q-rows.  Q frags from gmem; P C-frag pairs ARE the
// PV A-frag half2s (no relayout).  2-stage cp.async K/V halves.
// ---------------------------------------------------------------------------
constexpr int BQ = 64;
constexpr int BK = 64;
constexpr int NTILE = NS / BK;          // 32
constexpr int KP = 72;                  // pitch halves (144B = 36 banks)
constexpr int VP = 72;
constexpr int ATTN_SMEM_BYTES = (2 * BK * KP + 2 * NDH * VP) * 2;   // 36864

__global__ void __launch_bounds__(128, 3) attn_kernel(
        const float* __restrict__ amask, float* __restrict__ out) {
    extern __shared__ __half hsm[];
    __half* Ks = hsm;                         // [2][BK][KP]  token-major
    __half* Vs = hsm + 2 * BK * KP;           // [2][NDH][VP] d-major (V^T)

    int bh = blockIdx.y;
    int b  = bh >> 4;
    int h  = bh & 15;
    int q0 = blockIdx.x * BQ;
    int tid  = threadIdx.x;
    int w    = tid >> 5;
    int lane = tid & 31;
    int gid  = lane >> 2;
    int tig  = lane & 3;
    int l8  = lane & 7;
    int brow8 = ((lane >> 4) & 1) * 8;
    int bk8   = ((lane >> 3) & 1) * 8;

    const __half* Qg = g_q + (size_t)bh * NS * NDH;
    const __half* Kg = g_k + (size_t)bh * NS * NDH;
    const __half* Vg = g_v + (size_t)bh * NDH * NS;   // [d][s]

    auto issue_kv = [&](int t0, int st) {
#pragma unroll
        for (int u = 0; u < 8; ++u) {
            int idx = tid + u * 128;         // 0..1023: K chunks then V chunks
            int is_v = idx >> 9;             // 0 or 1
            int r2   = (idx & 511) >> 3;     // 0..63
            int c16  = idx & 7;              // 16B chunk (8 halves)
            if (!is_v)
                cp_async16(&Ks[(size_t)st * BK * KP + r2 * KP + c16 * 8],
                           &Kg[(size_t)(t0 + r2) * NDH + c16 * 8]);
            else
                cp_async16(&Vs[(size_t)st * NDH * VP + r2 * VP + c16 * 8],
                           &Vg[(size_t)r2 * NS + t0 + c16 * 8]);
        }
        cp_commit();
    };

    issue_kv(0, 0);

    // Q A-frags from gmem fp16 (4 k-chunks of 16): half2 loads
    unsigned a[4][4];
    {
        const __half* Qr0 = Qg + (size_t)(q0 + w * 16 + gid) * NDH;
        const __half* Qr8 = Qr0 + 8 * NDH;
#pragma unroll
        for (int kc = 0; kc < 4; ++kc) {
            a[kc][0] = *(const unsigned*)&Qr0[kc * 16 + 2 * tig];
            a[kc][1] = *(const unsigned*)&Qr8[kc * 16 + 2 * tig];
            a[kc][2] = *(const unsigned*)&Qr0[kc * 16 + 8 + 2 * tig];
            a[kc][3] = *(const unsigned*)&Qr8[kc * 16 + 8 + 2 * tig];
        }
    }

    float o[8][4];
#pragma unroll
    for (int j = 0; j < 8; ++j)
#pragma unroll
        for (int r = 0; r < 4; ++r) o[j][r] = 0.f;
    float mrow[2] = {-1e30f, -1e30f};
    float lrow[2] = {0.f, 0.f};

    for (int it = 0; it < NTILE; ++it) {
        cp_wait<0>();
        __syncthreads();
        if (it + 1 < NTILE) issue_kv((it + 1) * BK, (it + 1) & 1);
        int st = it & 1;
        const __half* Kp = &Ks[(size_t)st * BK * KP];
        const __half* Vp = &Vs[(size_t)st * NDH * VP];
        int t0 = it * BK;

        // S = Q @ K^T : B frags x4 serve two n8 tiles per call
        float s[8][4];
#pragma unroll
        for (int nt = 0; nt < 8; ++nt)
            s[nt][0] = s[nt][1] = s[nt][2] = s[nt][3] = 0.f;
#pragma unroll
        for (int ntp = 0; ntp < 4; ++ntp)
#pragma unroll
            for (int kc = 0; kc < 4; ++kc) {
                unsigned bf[4];
                ldsm_x4(bf, &Kp[(ntp * 16 + brow8 + l8) * KP + kc * 16 + bk8]);
                mma_f16(s[2 * ntp],     a[kc], bf[0], bf[1]);
                mma_f16(s[2 * ntp + 1], a[kc], bf[2], bf[3]);
            }

        // scale + mask + online softmax
        float mt0 = -1e30f, mt1 = -1e30f;
#pragma unroll
        for (int nt = 0; nt < 8; ++nt) {
            float2 mk = *(const float2*)&amask[b * NS + t0 + nt * 8 + 2 * tig];
            s[nt][0] = fmaf(s[nt][0], 0.125f, mk.x);
            s[nt][1] = fmaf(s[nt][1], 0.125f, mk.y);
            s[nt][2] = fmaf(s[nt][2], 0.125f, mk.x);
            s[nt][3] = fmaf(s[nt][3], 0.125f, mk.y);
            mt0 = fmaxf(mt0, fmaxf(s[nt][0], s[nt][1]));
            mt1 = fmaxf(mt1, fmaxf(s[nt][2], s[nt][3]));
        }
        mt0 = fmaxf(mt0, __shfl_xor_sync(0xffffffffu, mt0, 1));
        mt0 = fmaxf(mt0, __shfl_xor_sync(0xffffffffu, mt0, 2));
        mt1 = fmaxf(mt1, __shfl_xor_sync(0xffffffffu, mt1, 1));
        mt1 = fmaxf(mt1, __shfl_xor_sync(0xffffffffu, mt1, 2));

        float mn0 = fmaxf(mrow[0], mt0);
        float mn1 = fmaxf(mrow[1], mt1);
        float al0 = __expf(mrow[0] - mn0);
        float al1 = __expf(mrow[1] - mn1);
        mrow[0] = mn0; mrow[1] = mn1;
        lrow[0] *= al0; lrow[1] *= al1;
#pragma unroll
        for (int j = 0; j < 8; ++j) {
            o[j][0] *= al0; o[j][1] *= al0;
            o[j][2] *= al1; o[j][3] *= al1;
        }

        // exp -> half pairs (PV A-frags directly); l-sum over the SAME
        // half-rounded values so normalization cancels the rounding.
        unsigned pa[4][4];                  // [kc][a0..a3]
        float rs0 = 0.f, rs1 = 0.f;
#pragma unroll
        for (int nt = 0; nt < 8; ++nt) {
            float p0 = __expf(s[nt][0] - mrow[0]);
            float p1 = __expf(s[nt][1] - mrow[0]);
            float p2 = __expf(s[nt][2] - mrow[1]);
            float p3 = __expf(s[nt][3] - mrow[1]);
            unsigned lo = pack_h2(p0, p1);
            unsigned hi = pack_h2(p2, p3);
            int kc = nt >> 1;
            if ((nt & 1) == 0) { pa[kc][0] = lo; pa[kc][1] = hi; }
            else               { pa[kc][2] = lo; pa[kc][3] = hi; }
            __half2 hlo = *(__half2*)&lo, hhi = *(__half2*)&hi;
            rs0 += __low2float(hlo) + __high2float(hlo);
            rs1 += __low2float(hhi) + __high2float(hhi);
        }
        rs0 += __shfl_xor_sync(0xffffffffu, rs0, 1);
        rs0 += __shfl_xor_sync(0xffffffffu, rs0, 2);
        rs1 += __shfl_xor_sync(0xffffffffu, rs1, 1);
        rs1 += __shfl_xor_sync(0xffffffffu, rs1, 2);
        lrow[0] += rs0;
        lrow[1] += rs1;

        // O += P @ V : B frags from V^T, x4 serves two d8 tiles
#pragma unroll
        for (int jp = 0; jp < 4; ++jp)
#pragma unroll
            for (int kc = 0; kc < 4; ++kc) {
                unsigned bf[4];
                ldsm_x4(bf, &Vp[(jp * 16 + brow8 + l8) * VP + kc * 16 + bk8]);
                mma_f16(o[2 * jp],     pa[kc], bf[0], bf[1]);
                mma_f16(o[2 * jp + 1], pa[kc], bf[2], bf[3]);
            }
    }

    float inv0 = 1.f / lrow[0];
    float inv1 = 1.f / lrow[1];
    int r0 = q0 + w * 16 + gid;
#pragma unroll
    for (int j = 0; j < 8; ++j) {
        int col = h * NDH + j * 8 + 2 * tig;
        *(float2*)&out[((size_t)(b * NS + r0)) * NDV + col] =
            make_float2(o[j][0] * inv0, o[j][1] * inv0);
        *(float2*)&out[((size_t)(b * NS + r0 + 8)) * NDV + col] =
            make_float2(o[j][2] * inv1, o[j][3] * inv1);
    }
}

// ---------------------------------------------------------------------------
// Launch
// ---------------------------------------------------------------------------
extern "C" void kernel_launch(void* const* d_in, const int* in_sizes, int n_in,
                              void* d_out, int out_size) {
    const float* hid   = (const float*)d_in[0];
    const float* amask = (const float*)d_in[1];
    const float* txt   = (const float*)d_in[2];
    const float* tmask = (const float*)d_in[3];
    const float* Wq  = (const float*)d_in[4];
    const float* bq  = (const float*)d_in[5];
    const float* Wk  = (const float*)d_in[6];
    const float* bk  = (const float*)d_in[7];
    const float* Wv  = (const float*)d_in[8];
    const float* bv  = (const float*)d_in[9];
    const float* Wdq = (const float*)d_in[10];
    const float* bdq = (const float*)d_in[11];
    const float* Wdk = (const float*)d_in[12];
    const float* bdk = (const float*)d_in[13];
    float* out = (float*)d_out;

    cudaFuncSetAttribute(attn_kernel,
                         cudaFuncAttributeMaxDynamicSharedMemorySize,
                         ATTN_SMEM_BYTES);
    cudaFuncSetAttribute(qkv_kernel,
                         cudaFuncAttributeMaxDynamicSharedMemorySize,
                         QKV_SMEM_BYTES);

    wt_kernel<<<dim3(NDV / 32, NDV / 32, 3), dim3(32, 8)>>>(Wq, Wk, Wv);
    hidh_kernel<<<(NB * NS * NDV / 4 + 255) / 256, 256>>>(hid);
    pool_kernel<<<(NB * NDT + 255) / 256, 256>>>(txt, tmask);
    gate_kernel<<<dim3(NDV / 64, 2, NB), 256>>>(Wdq, bdq, Wdk, bdk);
    qkv_kernel<<<dim3(NDV / 128, (NB * NS) / 128, 3), 256, QKV_SMEM_BYTES>>>(
        bq, bk, bv);
    attn_kernel<<<dim3(NS / BQ, NB * NH), 128, ATTN_SMEM_BYTES>>>(amask, out);
}